// round 4
// baseline (speedup 1.0000x reference)
#include <cuda_runtime.h>
#include <cstdint>

#define GAMMA   0.01f
#define NROWS   8192
#define NSV     5000
#define DIM     256
#define CCLS    10
#define NVSEG   500
#define NPAIR   45
#define RDIM    9      // C-1

#define MB      64     // x rows per block
#define SN      128    // sv cols per s-tile (4 tiles cover 500, zero-padded)
#define KSTR    130    // padded smem stride for Ks / Ash (8B-aligned rows)

// ---------------- small scratch globals (no runtime alloc) ------------------
__device__ float g_T[NROWS * RDIM * CCLS];   // T[n][r][c], 2.95 MB
__device__ float g_xn[NROWS];
__device__ float g_svn[NSV];

// ---------------- f32x2 helpers (bit-exact dual fp32 FMA) -------------------
__device__ __forceinline__ void ffma2(uint64_t& d, uint64_t a, uint64_t b) {
    asm("fma.rn.f32x2 %0, %1, %2, %0;" : "+l"(d) : "l"(a), "l"(b));
}
__device__ __forceinline__ float2 unpack2(uint64_t v) {
    float2 r;
    asm("mov.b64 {%0, %1}, %2;" : "=f"(r.x), "=f"(r.y) : "l"(v));
    return r;
}

// ---------------- row-norm kernels ------------------------------------------
__global__ void row_norm_x_kernel(const float* __restrict__ src) {
    int row = blockIdx.x;
    float v = src[(size_t)row * DIM + threadIdx.x];
    v = v * v;
    #pragma unroll
    for (int off = 16; off > 0; off >>= 1)
        v += __shfl_xor_sync(0xFFFFFFFFu, v, off);
    __shared__ float red[8];
    int wid = threadIdx.x >> 5, lid = threadIdx.x & 31;
    if (lid == 0) red[wid] = v;
    __syncthreads();
    if (threadIdx.x == 0) {
        float s = 0.f;
        #pragma unroll
        for (int w = 0; w < 8; w++) s += red[w];
        g_xn[row] = s;
    }
}

__global__ void row_norm_sv_kernel(const float* __restrict__ src) {
    int row = blockIdx.x;
    float v = src[(size_t)row * DIM + threadIdx.x];
    v = v * v;
    #pragma unroll
    for (int off = 16; off > 0; off >>= 1)
        v += __shfl_xor_sync(0xFFFFFFFFu, v, off);
    __shared__ float red[8];
    int wid = threadIdx.x >> 5, lid = threadIdx.x & 31;
    if (lid == 0) red[wid] = v;
    __syncthreads();
    if (threadIdx.x == 0) {
        float s = 0.f;
        #pragma unroll
        for (int w = 0; w < 8; w++) s += red[w];
        g_svn[row] = s;
    }
}

// ---------------- fused GEMM + exp + segment contraction --------------------
// Block (bx, c): rows bm..bm+63 of x, class segment c.
// T[n, r, c] = sum_{m<500} exp(-g*||x_n - sv_{c*500+m}||^2) * a[r, c*500+m]
__global__ __launch_bounds__(256)
void svc_fused_kernel(const float* __restrict__ X, const float* __restrict__ SV,
                      const float* __restrict__ A)
{
    extern __shared__ float sm[];
    float* As  = sm;                       // [16][128] x-tile, duplicated pairs
    float* Bs  = As + 16 * 128;            // [16][SN]
    float* Ks  = Bs + 16 * SN;             // [MB][KSTR] exp'd kernel tile
    float* Ash = Ks + MB * KSTR;           // [RDIM][KSTR] dual-coef tile

    const int c   = blockIdx.y;
    const int bm  = blockIdx.x * MB;
    const int tid = threadIdx.x;
    const int tx  = tid & 15;              // col group: cols tx*8 .. tx*8+7
    const int ty  = tid >> 4;              // row group: rows ty*4 .. ty*4+3

    // T accumulators: slots tid, tid+256, tid+512 cover 576 = 64*9 outputs
    uint64_t tac[3];
    tac[0] = tac[1] = tac[2] = 0ull;

    for (int st = 0; st < 4; st++) {
        const int sbase = st * SN;

        // load a-tile (zero-padded beyond segment length 500)
        for (int i = tid; i < RDIM * SN; i += 256) {
            int r = i >> 7, sl = i & (SN - 1);
            int s = sbase + sl;
            Ash[r * KSTR + sl] = (s < NVSEG)
                ? A[(size_t)r * NSV + c * NVSEG + s] : 0.f;
        }

        uint64_t acc[4][4];
        #pragma unroll
        for (int i = 0; i < 4; i++)
            #pragma unroll
            for (int j = 0; j < 4; j++) acc[i][j] = 0ull;

        for (int k0 = 0; k0 < DIM; k0 += 16) {
            // A tile 64x16 -> duplicated pairs As[k][2m] = As[k][2m+1] = X[m,k]
            {
                int row = tid >> 2, c4 = tid & 3;
                float4 v = *reinterpret_cast<const float4*>(
                    &X[(size_t)(bm + row) * DIM + k0 + c4 * 4]);
                float* p = &As[(c4 * 4) * 128 + 2 * row];
                *reinterpret_cast<float2*>(p +   0) = make_float2(v.x, v.x);
                *reinterpret_cast<float2*>(p + 128) = make_float2(v.y, v.y);
                *reinterpret_cast<float2*>(p + 256) = make_float2(v.z, v.z);
                *reinterpret_cast<float2*>(p + 384) = make_float2(v.w, v.w);
            }
            // B tile SN x 16 (zero beyond NSV; cols past segment end get
            // garbage-but-finite values which are nulled by Ash zeros)
            #pragma unroll
            for (int t = 0; t < 2; t++) {
                int idx = tid + t * 256;
                int srow = idx >> 2, c4 = idx & 3;
                int svr = c * NVSEG + sbase + srow;
                float4 v = make_float4(0.f, 0.f, 0.f, 0.f);
                if (svr < NSV)
                    v = *reinterpret_cast<const float4*>(
                        &SV[(size_t)svr * DIM + k0 + c4 * 4]);
                Bs[(c4 * 4 + 0) * SN + srow] = v.x;
                Bs[(c4 * 4 + 1) * SN + srow] = v.y;
                Bs[(c4 * 4 + 2) * SN + srow] = v.z;
                Bs[(c4 * 4 + 3) * SN + srow] = v.w;
            }
            __syncthreads();

            #pragma unroll
            for (int k = 0; k < 16; k++) {
                const ulonglong2* pa2 =
                    reinterpret_cast<const ulonglong2*>(&As[k * 128 + 8 * ty]);
                const ulonglong2* pb2 =
                    reinterpret_cast<const ulonglong2*>(&Bs[k * SN + 8 * tx]);
                ulonglong2 a01 = pa2[0], a23 = pa2[1];
                ulonglong2 b01 = pb2[0], b23 = pb2[1];
                uint64_t ra[4] = {a01.x, a01.y, a23.x, a23.y};
                uint64_t rb[4] = {b01.x, b01.y, b23.x, b23.y};
                #pragma unroll
                for (int i = 0; i < 4; i++)
                    #pragma unroll
                    for (int jp = 0; jp < 4; jp++)
                        ffma2(acc[i][jp], ra[i], rb[jp]);
            }
            __syncthreads();
        }

        // epilogue: k = exp(2g*dot - g*(xn+svn)) -> Ks (0 where out of range)
        {
            float xn[4];
            #pragma unroll
            for (int i = 0; i < 4; i++) xn[i] = g_xn[bm + ty * 4 + i];
            #pragma unroll
            for (int jp = 0; jp < 4; jp++) {
                int cl  = tx * 8 + 2 * jp;
                int sg0 = c * NVSEG + sbase + cl;
                bool v0 = (sg0 < NSV), v1 = (sg0 + 1 < NSV);
                float sn0 = v0 ? g_svn[sg0]     : 0.f;
                float sn1 = v1 ? g_svn[sg0 + 1] : 0.f;
                #pragma unroll
                for (int i = 0; i < 4; i++) {
                    float2 d = unpack2(acc[i][jp]);
                    float k0v = v0 ? expf(2.f * GAMMA * d.x - GAMMA * (xn[i] + sn0)) : 0.f;
                    float k1v = v1 ? expf(2.f * GAMMA * d.y - GAMMA * (xn[i] + sn1)) : 0.f;
                    *reinterpret_cast<float2*>(&Ks[(ty * 4 + i) * KSTR + cl]) =
                        make_float2(k0v, k1v);
                }
            }
        }
        __syncthreads();

        // contraction: T[n][r] += sum_s Ks[n][s] * Ash[r][s]  (f32x2 pairs)
        #pragma unroll
        for (int sl = 0; sl < 3; sl++) {
            int j = tid + sl * 256;
            if (j < MB * RDIM) {
                int n = j / 9, r = j - n * 9;
                const uint64_t* kp =
                    reinterpret_cast<const uint64_t*>(&Ks[n * KSTR]);
                const uint64_t* ap =
                    reinterpret_cast<const uint64_t*>(&Ash[r * KSTR]);
                #pragma unroll 8
                for (int s2 = 0; s2 < SN / 2; s2++)
                    ffma2(tac[sl], kp[s2], ap[s2]);
            }
        }
        __syncthreads();   // before next tile overwrites Ks / Ash / As / Bs
    }

    // write T
    #pragma unroll
    for (int sl = 0; sl < 3; sl++) {
        int j = tid + sl * 256;
        if (j < MB * RDIM) {
            int n = j / 9, r = j - n * 9;
            float2 v = unpack2(tac[sl]);
            g_T[(size_t)(bm + n) * (RDIM * CCLS) + r * CCLS + c] = v.x + v.y;
        }
    }
}

// ---------------- pairwise vote + argmax (FLOAT output) ----------------------
__global__ void vote_kernel(const float* __restrict__ b, float* __restrict__ out,
                            int out_size) {
    int n = blockIdx.x * blockDim.x + threadIdx.x;
    if (n >= NROWS) return;
    float T[RDIM * CCLS];
    #pragma unroll
    for (int i = 0; i < RDIM * CCLS; i++)
        T[i] = g_T[(size_t)n * (RDIM * CCLS) + i];

    int counts[CCLS];
    #pragma unroll
    for (int k = 0; k < CCLS; k++) counts[k] = 0;

    int p = 0;
    #pragma unroll
    for (int i = 0; i < CCLS; i++) {
        #pragma unroll
        for (int j = i + 1; j < CCLS; j++) {
            float cv = T[i * CCLS + j] + T[(j - 1) * CCLS + i] + b[p];
            counts[(cv > 0.f) ? i : j]++;
            p++;
        }
    }
    int best = 0;
    #pragma unroll
    for (int cls = 1; cls < CCLS; cls++)
        if (counts[cls] > counts[best]) best = cls;

    float bestf = (float)best;
    if (n < out_size) out[n] = bestf;
    if (n + NROWS < out_size) out[n + NROWS] = bestf;
}

// ---------------- launch ------------------------------------------------------
#define FUSED_SMEM ((16*128 + 16*SN + MB*KSTR + RDIM*KSTR) * (int)sizeof(float))

extern "C" void kernel_launch(void* const* d_in, const int* in_sizes, int n_in,
                              void* d_out, int out_size) {
    // size-matched dispatch (all element counts distinct), positional fallback
    const float* x  = nullptr;   // 8192*256 = 2097152
    const float* sv = nullptr;   // 5000*256 = 1280000
    const float* a  = nullptr;   // 9*5000   = 45000
    const float* b  = nullptr;   // 45
    for (int i = 0; i < n_in; i++) {
        switch (in_sizes[i]) {
            case NROWS * DIM: x  = (const float*)d_in[i]; break;
            case NSV * DIM:   sv = (const float*)d_in[i]; break;
            case RDIM * NSV:  a  = (const float*)d_in[i]; break;
            case NPAIR:       b  = (const float*)d_in[i]; break;
            default: break;
        }
    }
    if (!x || !sv || !a || !b) {
        x = (const float*)d_in[0]; sv = (const float*)d_in[1];
        a = (const float*)d_in[2]; b  = (const float*)d_in[3];
    }
    float* out = (float*)d_out;   // output dtype: float32 (class ids as floats)

    cudaFuncSetAttribute(svc_fused_kernel,
                         cudaFuncAttributeMaxDynamicSharedMemorySize, FUSED_SMEM);

    row_norm_x_kernel<<<NROWS, 256>>>(x);
    row_norm_sv_kernel<<<NSV, 256>>>(sv);

    dim3 fgrid(NROWS / MB, CCLS);
    svc_fused_kernel<<<fgrid, 256, FUSED_SMEM>>>(x, sv, a);

    vote_kernel<<<(NROWS + 255) / 256, 256>>>(b, out, out_size);
}

// round 7
// speedup vs baseline: 1.0443x; 1.0443x over previous
#include <cuda_runtime.h>
#include <cstdint>

#define GAMMA   0.01f
#define NROWS   8192
#define NSV     5000
#define DIM     256
#define CCLS    10
#define NVSEG   500
#define NPAIR   45
#define RDIM    9      // C-1

#define MB      64     // x rows per block
#define SN      128    // sv cols per s-tile (4 tiles cover 500, zero-padded)
#define KSTR    130    // padded smem stride for Ks / Ash (8B-aligned rows)
#define TILEF   (16 * 128)   // floats per As/Bs buffer

// ---------------- small scratch globals (no runtime alloc) ------------------
__device__ float g_T[NROWS * RDIM * CCLS];   // T[n][r][c], 2.95 MB
__device__ float g_xn[NROWS];
__device__ float g_svn[NSV];

// ---------------- f32x2 helpers (bit-exact dual fp32 FMA) -------------------
__device__ __forceinline__ void ffma2(uint64_t& d, uint64_t a, uint64_t b) {
    asm("fma.rn.f32x2 %0, %1, %2, %0;" : "+l"(d) : "l"(a), "l"(b));
}
__device__ __forceinline__ float2 unpack2(uint64_t v) {
    float2 r;
    asm("mov.b64 {%0, %1}, %2;" : "=f"(r.x), "=f"(r.y) : "l"(v));
    return r;
}

// ---------------- row-norm kernels ------------------------------------------
__global__ void row_norm_x_kernel(const float* __restrict__ src) {
    int row = blockIdx.x;
    float v = src[(size_t)row * DIM + threadIdx.x];
    v = v * v;
    #pragma unroll
    for (int off = 16; off > 0; off >>= 1)
        v += __shfl_xor_sync(0xFFFFFFFFu, v, off);
    __shared__ float red[8];
    int wid = threadIdx.x >> 5, lid = threadIdx.x & 31;
    if (lid == 0) red[wid] = v;
    __syncthreads();
    if (threadIdx.x == 0) {
        float s = 0.f;
        #pragma unroll
        for (int w = 0; w < 8; w++) s += red[w];
        g_xn[row] = s;
    }
}

__global__ void row_norm_sv_kernel(const float* __restrict__ src) {
    int row = blockIdx.x;
    float v = src[(size_t)row * DIM + threadIdx.x];
    v = v * v;
    #pragma unroll
    for (int off = 16; off > 0; off >>= 1)
        v += __shfl_xor_sync(0xFFFFFFFFu, v, off);
    __shared__ float red[8];
    int wid = threadIdx.x >> 5, lid = threadIdx.x & 31;
    if (lid == 0) red[wid] = v;
    __syncthreads();
    if (threadIdx.x == 0) {
        float s = 0.f;
        #pragma unroll
        for (int w = 0; w < 8; w++) s += red[w];
        g_svn[row] = s;
    }
}

// ---------------- fused GEMM + exp + segment contraction --------------------
// Block (bx, c): rows bm..bm+63 of x, class segment c.
// T[n, r, c] = sum_{m<500} exp(-g*||x_n - sv_{c*500+m}||^2) * a[r, c*500+m]
// Double-buffered k-loop: LDG(next)->regs, compute(cur), STS->other, 1 sync.
__global__ __launch_bounds__(256, 2)
void svc_fused_kernel(const float* __restrict__ X, const float* __restrict__ SV,
                      const float* __restrict__ A)
{
    extern __shared__ float sm[];
    float* As  = sm;                       // 2 x [16][128] x-tile, dup pairs
    float* Bs  = As + 2 * TILEF;           // 2 x [16][SN]
    float* Ks  = Bs + 2 * TILEF;           // [MB][KSTR] exp'd kernel tile
    float* Ash = Ks + MB * KSTR;           // [RDIM][KSTR] dual-coef tile

    const int c   = blockIdx.y;
    const int bm  = blockIdx.x * MB;
    const int tid = threadIdx.x;
    const int tx  = tid & 15;              // col group: cols tx*8 .. tx*8+7
    const int ty  = tid >> 4;              // row group: rows ty*4 .. ty*4+3

    // per-thread staging indices (constant across iterations)
    const int a_row = tid >> 2, a_c4 = tid & 3;     // A: 1 float4
    const int b_row0 = tid >> 2,       b_c40 = tid & 3;        // B: 2 float4
    const int b_row1 = (tid + 256) >> 2, b_c41 = tid & 3;

    // T accumulators: slots tid, tid+256, tid+512 cover 576 = 64*9 outputs
    uint64_t tac[3];
    tac[0] = tac[1] = tac[2] = 0ull;

    for (int st = 0; st < 4; st++) {
        const int sbase = st * SN;

        // load a-tile (zero-padded beyond segment length 500)
        for (int i = tid; i < RDIM * SN; i += 256) {
            int r = i >> 7, sl = i & (SN - 1);
            int s = sbase + sl;
            Ash[r * KSTR + sl] = (s < NVSEG)
                ? A[(size_t)r * NSV + c * NVSEG + s] : 0.f;
        }

        uint64_t acc[4][4];
        #pragma unroll
        for (int i = 0; i < 4; i++)
            #pragma unroll
            for (int j = 0; j < 4; j++) acc[i][j] = 0ull;

        // ---- prologue: load k0=0 tile into regs, stage to buf 0 ----
        float4 pa, pb0, pb1;
        {
            pa = *reinterpret_cast<const float4*>(
                &X[(size_t)(bm + a_row) * DIM + 0 + a_c4 * 4]);
            int svr0 = c * NVSEG + sbase + b_row0;
            int svr1 = c * NVSEG + sbase + b_row1;
            pb0 = make_float4(0.f, 0.f, 0.f, 0.f);
            pb1 = make_float4(0.f, 0.f, 0.f, 0.f);
            if (svr0 < NSV)
                pb0 = *reinterpret_cast<const float4*>(
                    &SV[(size_t)svr0 * DIM + 0 + b_c40 * 4]);
            if (svr1 < NSV)
                pb1 = *reinterpret_cast<const float4*>(
                    &SV[(size_t)svr1 * DIM + 0 + b_c41 * 4]);
        }
        {
            float* Ab = As;                 // buffer 0
            float* Bb = Bs;
            float* p = &Ab[(a_c4 * 4) * 128 + 2 * a_row];
            *reinterpret_cast<float2*>(p +   0) = make_float2(pa.x, pa.x);
            *reinterpret_cast<float2*>(p + 128) = make_float2(pa.y, pa.y);
            *reinterpret_cast<float2*>(p + 256) = make_float2(pa.z, pa.z);
            *reinterpret_cast<float2*>(p + 384) = make_float2(pa.w, pa.w);
            Bb[(b_c40 * 4 + 0) * SN + b_row0] = pb0.x;
            Bb[(b_c40 * 4 + 1) * SN + b_row0] = pb0.y;
            Bb[(b_c40 * 4 + 2) * SN + b_row0] = pb0.z;
            Bb[(b_c40 * 4 + 3) * SN + b_row0] = pb0.w;
            Bb[(b_c41 * 4 + 0) * SN + b_row1] = pb1.x;
            Bb[(b_c41 * 4 + 1) * SN + b_row1] = pb1.y;
            Bb[(b_c41 * 4 + 2) * SN + b_row1] = pb1.z;
            Bb[(b_c41 * 4 + 3) * SN + b_row1] = pb1.w;
        }
        __syncthreads();

        // ---- pipelined k-loop: 16 steps of BK=16 ----
        for (int kk = 0; kk < 16; kk++) {
            const int buf = kk & 1;
            const float* Ab = As + buf * TILEF;
            const float* Bb = Bs + buf * TILEF;

            // prefetch next tile into registers (hidden under compute)
            if (kk < 15) {
                int k0n = (kk + 1) * 16;
                pa = *reinterpret_cast<const float4*>(
                    &X[(size_t)(bm + a_row) * DIM + k0n + a_c4 * 4]);
                int svr0 = c * NVSEG + sbase + b_row0;
                int svr1 = c * NVSEG + sbase + b_row1;
                pb0 = make_float4(0.f, 0.f, 0.f, 0.f);
                pb1 = make_float4(0.f, 0.f, 0.f, 0.f);
                if (svr0 < NSV)
                    pb0 = *reinterpret_cast<const float4*>(
                        &SV[(size_t)svr0 * DIM + k0n + b_c40 * 4]);
                if (svr1 < NSV)
                    pb1 = *reinterpret_cast<const float4*>(
                        &SV[(size_t)svr1 * DIM + k0n + b_c41 * 4]);
            }

            // compute current buffer
            #pragma unroll
            for (int k = 0; k < 16; k++) {
                const ulonglong2* pa2 =
                    reinterpret_cast<const ulonglong2*>(&Ab[k * 128 + 8 * ty]);
                const ulonglong2* pb2 =
                    reinterpret_cast<const ulonglong2*>(&Bb[k * SN + 8 * tx]);
                ulonglong2 a01 = pa2[0], a23 = pa2[1];
                ulonglong2 b01 = pb2[0], b23 = pb2[1];
                uint64_t ra[4] = {a01.x, a01.y, a23.x, a23.y};
                uint64_t rb[4] = {b01.x, b01.y, b23.x, b23.y};
                #pragma unroll
                for (int i = 0; i < 4; i++)
                    #pragma unroll
                    for (int jp = 0; jp < 4; jp++)
                        ffma2(acc[i][jp], ra[i], rb[jp]);
            }

            // stage prefetched tile into the other buffer
            if (kk < 15) {
                float* Aw = As + (buf ^ 1) * TILEF;
                float* Bw = Bs + (buf ^ 1) * TILEF;
                float* p = &Aw[(a_c4 * 4) * 128 + 2 * a_row];
                *reinterpret_cast<float2*>(p +   0) = make_float2(pa.x, pa.x);
                *reinterpret_cast<float2*>(p + 128) = make_float2(pa.y, pa.y);
                *reinterpret_cast<float2*>(p + 256) = make_float2(pa.z, pa.z);
                *reinterpret_cast<float2*>(p + 384) = make_float2(pa.w, pa.w);
                Bw[(b_c40 * 4 + 0) * SN + b_row0] = pb0.x;
                Bw[(b_c40 * 4 + 1) * SN + b_row0] = pb0.y;
                Bw[(b_c40 * 4 + 2) * SN + b_row0] = pb0.z;
                Bw[(b_c40 * 4 + 3) * SN + b_row0] = pb0.w;
                Bw[(b_c41 * 4 + 0) * SN + b_row1] = pb1.x;
                Bw[(b_c41 * 4 + 1) * SN + b_row1] = pb1.y;
                Bw[(b_c41 * 4 + 2) * SN + b_row1] = pb1.z;
                Bw[(b_c41 * 4 + 3) * SN + b_row1] = pb1.w;
            }
            __syncthreads();
        }

        // epilogue: k = exp(2g*dot - g*(xn+svn)) -> Ks (0 where out of range)
        {
            float xn[4];
            #pragma unroll
            for (int i = 0; i < 4; i++) xn[i] = g_xn[bm + ty * 4 + i];
            #pragma unroll
            for (int jp = 0; jp < 4; jp++) {
                int cl  = tx * 8 + 2 * jp;
                int sg0 = c * NVSEG + sbase + cl;
                bool v0 = (sg0 < NSV), v1 = (sg0 + 1 < NSV);
                float sn0 = v0 ? g_svn[sg0]     : 0.f;
                float sn1 = v1 ? g_svn[sg0 + 1] : 0.f;
                #pragma unroll
                for (int i = 0; i < 4; i++) {
                    float2 d = unpack2(acc[i][jp]);
                    float k0v = v0 ? expf(2.f * GAMMA * d.x - GAMMA * (xn[i] + sn0)) : 0.f;
                    float k1v = v1 ? expf(2.f * GAMMA * d.y - GAMMA * (xn[i] + sn1)) : 0.f;
                    *reinterpret_cast<float2*>(&Ks[(ty * 4 + i) * KSTR + cl]) =
                        make_float2(k0v, k1v);
                }
            }
        }
        __syncthreads();

        // contraction: T[n][r] += sum_s Ks[n][s] * Ash[r][s]  (f32x2 pairs)
        #pragma unroll
        for (int sl = 0; sl < 3; sl++) {
            int j = tid + sl * 256;
            if (j < MB * RDIM) {
                int n = j / 9, r = j - n * 9;
                const uint64_t* kp =
                    reinterpret_cast<const uint64_t*>(&Ks[n * KSTR]);
                const uint64_t* ap =
                    reinterpret_cast<const uint64_t*>(&Ash[r * KSTR]);
                #pragma unroll 8
                for (int s2 = 0; s2 < SN / 2; s2++)
                    ffma2(tac[sl], kp[s2], ap[s2]);
            }
        }
        __syncthreads();   // before next tile overwrites Ks / Ash / As / Bs
    }

    // write T
    #pragma unroll
    for (int sl = 0; sl < 3; sl++) {
        int j = tid + sl * 256;
        if (j < MB * RDIM) {
            int n = j / 9, r = j - n * 9;
            float2 v = unpack2(tac[sl]);
            g_T[(size_t)(bm + n) * (RDIM * CCLS) + r * CCLS + c] = v.x + v.y;
        }
    }
}

// ---------------- pairwise vote + argmax (FLOAT output) ----------------------
__global__ void vote_kernel(const float* __restrict__ b, float* __restrict__ out,
                            int out_size) {
    int n = blockIdx.x * blockDim.x + threadIdx.x;
    if (n >= NROWS) return;
    float T[RDIM * CCLS];
    #pragma unroll
    for (int i = 0; i < RDIM * CCLS; i++)
        T[i] = g_T[(size_t)n * (RDIM * CCLS) + i];

    int counts[CCLS];
    #pragma unroll
    for (int k = 0; k < CCLS; k++) counts[k] = 0;

    int p = 0;
    #pragma unroll
    for (int i = 0; i < CCLS; i++) {
        #pragma unroll
        for (int j = i + 1; j < CCLS; j++) {
            float cv = T[i * CCLS + j] + T[(j - 1) * CCLS + i] + b[p];
            counts[(cv > 0.f) ? i : j]++;
            p++;
        }
    }
    int best = 0;
    #pragma unroll
    for (int cls = 1; cls < CCLS; cls++)
        if (counts[cls] > counts[best]) best = cls;

    float bestf = (float)best;
    if (n < out_size) out[n] = bestf;
    if (n + NROWS < out_size) out[n + NROWS] = bestf;
}

// ---------------- launch ------------------------------------------------------
#define FUSED_SMEM ((2*TILEF + 2*TILEF + MB*KSTR + RDIM*KSTR) * (int)sizeof(float))

extern "C" void kernel_launch(void* const* d_in, const int* in_sizes, int n_in,
                              void* d_out, int out_size) {
    // size-matched dispatch (all element counts distinct), positional fallback
    const float* x  = nullptr;   // 8192*256 = 2097152
    const float* sv = nullptr;   // 5000*256 = 1280000
    const float* a  = nullptr;   // 9*5000   = 45000
    const float* b  = nullptr;   // 45
    for (int i = 0; i < n_in; i++) {
        switch (in_sizes[i]) {
            case NROWS * DIM: x  = (const float*)d_in[i]; break;
            case NSV * DIM:   sv = (const float*)d_in[i]; break;
            case RDIM * NSV:  a  = (const float*)d_in[i]; break;
            case NPAIR:       b  = (const float*)d_in[i]; break;
            default: break;
        }
    }
    if (!x || !sv || !a || !b) {
        x = (const float*)d_in[0]; sv = (const float*)d_in[1];
        a = (const float*)d_in[2]; b  = (const float*)d_in[3];
    }
    float* out = (float*)d_out;   // output dtype: float32 (class ids as floats)

    cudaFuncSetAttribute(svc_fused_kernel,
                         cudaFuncAttributeMaxDynamicSharedMemorySize, FUSED_SMEM);

    row_norm_x_kernel<<<NROWS, 256>>>(x);
    row_norm_sv_kernel<<<NSV, 256>>>(sv);

    dim3 fgrid(NROWS / MB, CCLS);
    svc_fused_kernel<<<fgrid, 256, FUSED_SMEM>>>(x, sv, a);

    vote_kernel<<<(NROWS + 255) / 256, 256>>>(b, out, out_size);
}

// round 8
// speedup vs baseline: 1.0549x; 1.0101x over previous
#include <cuda_runtime.h>
#include <cstdint>

#define GAMMA   0.01f
#define NROWS   8192
#define NSV     5000
#define DIM     256
#define CCLS    10
#define NVSEG   500
#define NPAIR   45
#define RDIM    9      // C-1

#define MB      64     // x rows per block
#define SN      128    // sv cols per s-tile (4 tiles cover 500, zero-padded)
#define KSTR    130    // padded smem stride for Ks / Ash
#define TILEF   (16 * 128)   // floats per As/Bs buffer

// ---------------- scratch globals (no runtime alloc) -------------------------
__device__ float g_T[NROWS * RDIM * CCLS];   // T[n][r][c], 2.95 MB
__device__ int   g_ticket[NROWS / MB];       // zero-init; self-resetting

// ---------------- f32x2 helpers (bit-exact dual fp32 FMA) -------------------
__device__ __forceinline__ void ffma2(uint64_t& d, uint64_t a, uint64_t b) {
    asm("fma.rn.f32x2 %0, %1, %2, %0;" : "+l"(d) : "l"(a), "l"(b));
}
__device__ __forceinline__ float2 unpack2(uint64_t v) {
    float2 r;
    asm("mov.b64 {%0, %1}, %2;" : "=f"(r.x), "=f"(r.y) : "l"(v));
    return r;
}
__device__ __forceinline__ float dot4(float4 v) {
    return v.x * v.x + v.y * v.y + v.z * v.z + v.w * v.w;
}

// ---------------- single fused kernel ----------------------------------------
// Block (bx, c): rows bm..bm+63 of x, class segment c.
//   - norms of its x rows / sv rows computed inline from the staged tiles
//   - GEMM + exp + per-class contraction -> g_T
//   - last block per bm (atomic ticket) computes votes + writes output
__global__ __launch_bounds__(256, 2)
void svc_all_kernel(const float* __restrict__ X, const float* __restrict__ SV,
                    const float* __restrict__ A, const float* __restrict__ Bv,
                    float* __restrict__ out, int out_size)
{
    extern __shared__ float sm[];
    float* As     = sm;                      // 2 x [16][128] x-tile, dup pairs
    float* Bs     = As + 2 * TILEF;          // 2 x [16][SN]
    float* Ks     = Bs + 2 * TILEF;          // [MB][KSTR] exp'd kernel tile
    float* Ash    = Ks + MB * KSTR;          // [RDIM][KSTR] dual-coef tile
    float* xn_sh  = Ash + RDIM * KSTR;       // [64]  x row norms
    float* svn_sh = xn_sh + MB;              // [128] sv row norms (this panel)
    __shared__ int t_rank;

    const int c   = blockIdx.y;
    const int bm  = blockIdx.x * MB;
    const int tid = threadIdx.x;
    const int tx  = tid & 15;                // col group: cols tx*8 .. tx*8+7
    const int ty  = tid >> 4;                // row group: rows ty*4 .. ty*4+3

    const int a_row  = tid >> 2, a_c4 = tid & 3;      // A: 1 float4 / thread
    const int b_row0 = tid >> 2;                      // B: 2 float4 / thread
    const int b_row1 = 64 + (tid >> 2);
    const int b_c4   = tid & 3;

    float xa_acc = 0.f;                      // x-norm partial (st==0 only)

    uint64_t tac[3];
    tac[0] = tac[1] = tac[2] = 0ull;

    for (int st = 0; st < 4; st++) {
        const int sbase = st * SN;
        float sn0_acc = 0.f, sn1_acc = 0.f;  // sv-norm partials for this panel

        // load a-tile (zero-padded beyond segment length 500)
        for (int i = tid; i < RDIM * SN; i += 256) {
            int r = i >> 7, sl = i & (SN - 1);
            int s = sbase + sl;
            Ash[r * KSTR + sl] = (s < NVSEG)
                ? A[(size_t)r * NSV + c * NVSEG + s] : 0.f;
        }

        uint64_t acc[4][4];
        #pragma unroll
        for (int i = 0; i < 4; i++)
            #pragma unroll
            for (int j = 0; j < 4; j++) acc[i][j] = 0ull;

        // ---- prologue: load k0=0 tile, accumulate norms, stage buf 0 ----
        float4 pa, pb0, pb1;
        {
            pa = *reinterpret_cast<const float4*>(
                &X[(size_t)(bm + a_row) * DIM + 0 + a_c4 * 4]);
            int svr0 = c * NVSEG + sbase + b_row0;
            int svr1 = c * NVSEG + sbase + b_row1;
            pb0 = make_float4(0.f, 0.f, 0.f, 0.f);
            pb1 = make_float4(0.f, 0.f, 0.f, 0.f);
            if (svr0 < NSV)
                pb0 = *reinterpret_cast<const float4*>(
                    &SV[(size_t)svr0 * DIM + 0 + b_c4 * 4]);
            if (svr1 < NSV)
                pb1 = *reinterpret_cast<const float4*>(
                    &SV[(size_t)svr1 * DIM + 0 + b_c4 * 4]);
            if (st == 0) xa_acc += dot4(pa);
            sn0_acc += dot4(pb0);
            sn1_acc += dot4(pb1);
        }
        {
            float* Ab = As;                  // buffer 0
            float* Bb = Bs;
            float* p = &Ab[(a_c4 * 4) * 128 + 2 * a_row];
            *reinterpret_cast<float2*>(p +   0) = make_float2(pa.x, pa.x);
            *reinterpret_cast<float2*>(p + 128) = make_float2(pa.y, pa.y);
            *reinterpret_cast<float2*>(p + 256) = make_float2(pa.z, pa.z);
            *reinterpret_cast<float2*>(p + 384) = make_float2(pa.w, pa.w);
            Bb[(b_c4 * 4 + 0) * SN + b_row0] = pb0.x;
            Bb[(b_c4 * 4 + 1) * SN + b_row0] = pb0.y;
            Bb[(b_c4 * 4 + 2) * SN + b_row0] = pb0.z;
            Bb[(b_c4 * 4 + 3) * SN + b_row0] = pb0.w;
            Bb[(b_c4 * 4 + 0) * SN + b_row1] = pb1.x;
            Bb[(b_c4 * 4 + 1) * SN + b_row1] = pb1.y;
            Bb[(b_c4 * 4 + 2) * SN + b_row1] = pb1.z;
            Bb[(b_c4 * 4 + 3) * SN + b_row1] = pb1.w;
        }
        __syncthreads();

        // ---- pipelined k-loop: 16 steps of BK=16 ----
        for (int kk = 0; kk < 16; kk++) {
            const int buf = kk & 1;
            const float* Ab = As + buf * TILEF;
            const float* Bb = Bs + buf * TILEF;

            if (kk < 15) {
                int k0n = (kk + 1) * 16;
                pa = *reinterpret_cast<const float4*>(
                    &X[(size_t)(bm + a_row) * DIM + k0n + a_c4 * 4]);
                int svr0 = c * NVSEG + sbase + b_row0;
                int svr1 = c * NVSEG + sbase + b_row1;
                pb0 = make_float4(0.f, 0.f, 0.f, 0.f);
                pb1 = make_float4(0.f, 0.f, 0.f, 0.f);
                if (svr0 < NSV)
                    pb0 = *reinterpret_cast<const float4*>(
                        &SV[(size_t)svr0 * DIM + k0n + b_c4 * 4]);
                if (svr1 < NSV)
                    pb1 = *reinterpret_cast<const float4*>(
                        &SV[(size_t)svr1 * DIM + k0n + b_c4 * 4]);
                if (st == 0) xa_acc += dot4(pa);
                sn0_acc += dot4(pb0);
                sn1_acc += dot4(pb1);
            }

            #pragma unroll
            for (int k = 0; k < 16; k++) {
                const ulonglong2* pa2 =
                    reinterpret_cast<const ulonglong2*>(&Ab[k * 128 + 8 * ty]);
                const ulonglong2* pb2 =
                    reinterpret_cast<const ulonglong2*>(&Bb[k * SN + 8 * tx]);
                ulonglong2 a01 = pa2[0], a23 = pa2[1];
                ulonglong2 b01 = pb2[0], b23 = pb2[1];
                uint64_t ra[4] = {a01.x, a01.y, a23.x, a23.y};
                uint64_t rb[4] = {b01.x, b01.y, b23.x, b23.y};
                #pragma unroll
                for (int i = 0; i < 4; i++)
                    #pragma unroll
                    for (int jp = 0; jp < 4; jp++)
                        ffma2(acc[i][jp], ra[i], rb[jp]);
            }

            if (kk < 15) {
                float* Aw = As + (buf ^ 1) * TILEF;
                float* Bw = Bs + (buf ^ 1) * TILEF;
                float* p = &Aw[(a_c4 * 4) * 128 + 2 * a_row];
                *reinterpret_cast<float2*>(p +   0) = make_float2(pa.x, pa.x);
                *reinterpret_cast<float2*>(p + 128) = make_float2(pa.y, pa.y);
                *reinterpret_cast<float2*>(p + 256) = make_float2(pa.z, pa.z);
                *reinterpret_cast<float2*>(p + 384) = make_float2(pa.w, pa.w);
                Bw[(b_c4 * 4 + 0) * SN + b_row0] = pb0.x;
                Bw[(b_c4 * 4 + 1) * SN + b_row0] = pb0.y;
                Bw[(b_c4 * 4 + 2) * SN + b_row0] = pb0.z;
                Bw[(b_c4 * 4 + 3) * SN + b_row0] = pb0.w;
                Bw[(b_c4 * 4 + 0) * SN + b_row1] = pb1.x;
                Bw[(b_c4 * 4 + 1) * SN + b_row1] = pb1.y;
                Bw[(b_c4 * 4 + 2) * SN + b_row1] = pb1.z;
                Bw[(b_c4 * 4 + 3) * SN + b_row1] = pb1.w;
            }
            __syncthreads();
        }

        // ---- reduce norm partials (quad shuffle over c4) ----
        {
            float s0 = sn0_acc, s1 = sn1_acc;
            s0 += __shfl_down_sync(0xFFFFFFFFu, s0, 2, 4);
            s0 += __shfl_down_sync(0xFFFFFFFFu, s0, 1, 4);
            s1 += __shfl_down_sync(0xFFFFFFFFu, s1, 2, 4);
            s1 += __shfl_down_sync(0xFFFFFFFFu, s1, 1, 4);
            if (b_c4 == 0) {
                svn_sh[b_row0] = s0;
                svn_sh[b_row1] = s1;
            }
            if (st == 0) {
                float xv = xa_acc;
                xv += __shfl_down_sync(0xFFFFFFFFu, xv, 2, 4);
                xv += __shfl_down_sync(0xFFFFFFFFu, xv, 1, 4);
                if (a_c4 == 0) xn_sh[a_row] = xv;
            }
        }
        __syncthreads();

        // ---- epilogue: k = exp(2g*dot - g*(xn+svn)) -> Ks ----
        {
            float xn[4];
            #pragma unroll
            for (int i = 0; i < 4; i++) xn[i] = xn_sh[ty * 4 + i];
            #pragma unroll
            for (int jp = 0; jp < 4; jp++) {
                int cl  = tx * 8 + 2 * jp;
                int sg0 = c * NVSEG + sbase + cl;
                bool v0 = (sg0 < NSV), v1 = (sg0 + 1 < NSV);
                float sn0 = svn_sh[cl];
                float sn1 = svn_sh[cl + 1];
                #pragma unroll
                for (int i = 0; i < 4; i++) {
                    float2 d = unpack2(acc[i][jp]);
                    float k0v = v0 ? expf(2.f * GAMMA * d.x - GAMMA * (xn[i] + sn0)) : 0.f;
                    float k1v = v1 ? expf(2.f * GAMMA * d.y - GAMMA * (xn[i] + sn1)) : 0.f;
                    *reinterpret_cast<float2*>(&Ks[(ty * 4 + i) * KSTR + cl]) =
                        make_float2(k0v, k1v);
                }
            }
        }
        __syncthreads();

        // ---- contraction: T[n][r] += sum_s Ks[n][s] * Ash[r][s] ----
        #pragma unroll
        for (int sl = 0; sl < 3; sl++) {
            int j = tid + sl * 256;
            if (j < MB * RDIM) {
                int n = j / 9, r = j - n * 9;
                const uint64_t* kp =
                    reinterpret_cast<const uint64_t*>(&Ks[n * KSTR]);
                const uint64_t* ap =
                    reinterpret_cast<const uint64_t*>(&Ash[r * KSTR]);
                #pragma unroll 8
                for (int s2 = 0; s2 < SN / 2; s2++)
                    ffma2(tac[sl], kp[s2], ap[s2]);
            }
        }
        __syncthreads();
    }

    // ---- write T slice ----
    #pragma unroll
    for (int sl = 0; sl < 3; sl++) {
        int j = tid + sl * 256;
        if (j < MB * RDIM) {
            int n = j / 9, r = j - n * 9;
            float2 v = unpack2(tac[sl]);
            g_T[(size_t)(bm + n) * (RDIM * CCLS) + r * CCLS + c] = v.x + v.y;
        }
    }

    // ---- atomic ticket: last of the 10 class-blocks for this bm votes ----
    __threadfence();
    if (tid == 0) t_rank = atomicAdd(&g_ticket[blockIdx.x], 1);
    __syncthreads();
    if (t_rank == CCLS - 1) {
        __threadfence();   // acquire: other blocks' g_T writes now visible
        if (tid < MB) {
            int n = bm + tid;
            float T[RDIM * CCLS];
            #pragma unroll
            for (int i = 0; i < RDIM * CCLS; i++)
                T[i] = g_T[(size_t)n * (RDIM * CCLS) + i];

            int counts[CCLS];
            #pragma unroll
            for (int k = 0; k < CCLS; k++) counts[k] = 0;

            int p = 0;
            #pragma unroll
            for (int i = 0; i < CCLS; i++) {
                #pragma unroll
                for (int j = i + 1; j < CCLS; j++) {
                    float cv = T[i * CCLS + j] + T[(j - 1) * CCLS + i] + Bv[p];
                    counts[(cv > 0.f) ? i : j]++;
                    p++;
                }
            }
            int best = 0;
            #pragma unroll
            for (int cls = 1; cls < CCLS; cls++)
                if (counts[cls] > counts[best]) best = cls;

            float bestf = (float)best;
            if (n < out_size) out[n] = bestf;
            if (n + NROWS < out_size) out[n + NROWS] = bestf;
        }
        if (tid == 0) g_ticket[blockIdx.x] = 0;   // reset for next replay
    }
}

// ---------------- launch ------------------------------------------------------
#define FUSED_SMEM ((2*TILEF + 2*TILEF + MB*KSTR + RDIM*KSTR + MB + SN) \
                    * (int)sizeof(float))

extern "C" void kernel_launch(void* const* d_in, const int* in_sizes, int n_in,
                              void* d_out, int out_size) {
    // size-matched dispatch (all element counts distinct), positional fallback
    const float* x  = nullptr;   // 8192*256 = 2097152
    const float* sv = nullptr;   // 5000*256 = 1280000
    const float* a  = nullptr;   // 9*5000   = 45000
    const float* b  = nullptr;   // 45
    for (int i = 0; i < n_in; i++) {
        switch (in_sizes[i]) {
            case NROWS * DIM: x  = (const float*)d_in[i]; break;
            case NSV * DIM:   sv = (const float*)d_in[i]; break;
            case RDIM * NSV:  a  = (const float*)d_in[i]; break;
            case NPAIR:       b  = (const float*)d_in[i]; break;
            default: break;
        }
    }
    if (!x || !sv || !a || !b) {
        x = (const float*)d_in[0]; sv = (const float*)d_in[1];
        a = (const float*)d_in[2]; b  = (const float*)d_in[3];
    }
    float* out = (float*)d_out;   // output dtype: float32 (class ids as floats)

    cudaFuncSetAttribute(svc_all_kernel,
                         cudaFuncAttributeMaxDynamicSharedMemorySize, FUSED_SMEM);

    dim3 fgrid(NROWS / MB, CCLS);
    svc_all_kernel<<<fgrid, 256, FUSED_SMEM>>>(x, sv, a, b, out, out_size);
}